// round 4
// baseline (speedup 1.0000x reference)
#include <cuda_runtime.h>
#include <cstdint>
#include <cstddef>

#define D    128
#define DE   32
#define HIDN 512
#define MAXN 100000
#define MAXE 1000000
#define EPSF 1e-5f

#define HSTR 133   // padded row stride for LN buffers (conflict-free column reads)
#define ASTR 36    // padded row stride for A-staging tiles (float4-aligned)
#define TSTR 132   // padded row stride for attr transpose tile

// ---------------- scratch (static device allocations; no cudaMalloc) ------------
__device__ float g_fold[289 * D];         // [W1;b1] @ W2  (+b2 on row 288)
__device__ float g_A[(size_t)MAXN * D];   // x @ (W1a@W2)  gathered by src
__device__ float g_B[(size_t)MAXN * D];   // x @ (W1b@W2)  gathered by dst
__device__ float g_agg[(size_t)MAXN * D]; // segment_sum(sigmoid(z))
__device__ float g_cnt[MAXN];
__device__ int   g_idx64;                 // 1 if edge_index buffer is int64

__device__ __forceinline__ float sigm(float z) {
    return __fdividef(1.0f, 1.0f + __expf(-z));
}

__device__ __forceinline__ void red_add_v4(float* p, float a, float b, float c, float d) {
    asm volatile("red.global.add.v4.f32 [%0], {%1, %2, %3, %4};"
                 :: "l"(p), "f"(a), "f"(b), "f"(c), "f"(d) : "memory");
}

// ---------------- K0: detect edge_index dtype (int64 vs int32) ------------------
// int64 little-endian values < 2^31 have every odd 32-bit word == 0.
// For int32 data those words are independent indices (P(all 0) ~ 0).
__global__ void detect_idx_kernel(const int* __restrict__ eidx_w32, int Ecnt)
{
    if (threadIdx.x == 0 && blockIdx.x == 0) {
        int is64 = 1;
        int lim = (Ecnt < 64) ? Ecnt : 64;
        for (int i = 0; i < lim; i++)
            if (eidx_w32[2 * i + 1] != 0) { is64 = 0; break; }
        g_idx64 = is64;
    }
}

// ---------------- K1: fold kernel  C[289x128] = [W1;b1] @ W2 (+b2 on bias row) ---
__global__ __launch_bounds__(256) void fold_kernel(
    const float* __restrict__ W1, const float* __restrict__ b1,
    const float* __restrict__ W2, const float* __restrict__ b2)
{
    __shared__ float aS[128 * ASTR];
    __shared__ float wS[32 * D];
    int tid = threadIdx.x;
    int tx = tid & 15, ty = tid >> 4;
    int r = ty * 8, c = tx * 8;
    int i0 = blockIdx.x * 128;

    float acc[8][8];
#pragma unroll
    for (int i = 0; i < 8; i++)
#pragma unroll
        for (int j = 0; j < 8; j++) acc[i][j] = 0.f;

    for (int k0 = 0; k0 < 128; k0 += 32) {
#pragma unroll
        for (int l = 0; l < 4; l++) {
            int gid = tid + l * 256;
            int row = gid >> 3, c4 = (gid & 7) << 2;
            int gi = i0 + row;
            float4 v = make_float4(0.f, 0.f, 0.f, 0.f);
            if (gi < 288)       v = *(const float4*)&W1[gi * D + k0 + c4];
            else if (gi == 288) v = *(const float4*)&b1[k0 + c4];
            *(float4*)&aS[row * ASTR + c4] = v;
        }
#pragma unroll
        for (int l = 0; l < 4; l++) {
            int gid = tid + l * 256;
            int kk = gid >> 5, j4 = (gid & 31) << 2;
            *(float4*)&wS[kk * D + j4] = *(const float4*)&W2[(k0 + kk) * D + j4];
        }
        __syncthreads();
#pragma unroll 4
        for (int kk = 0; kk < 32; kk++) {
            float a[8], b[8];
#pragma unroll
            for (int i = 0; i < 8; i++) a[i] = aS[(r + i) * ASTR + kk];
            *(float4*)&b[0] = *(float4*)&wS[kk * D + c];
            *(float4*)&b[4] = *(float4*)&wS[kk * D + c + 4];
#pragma unroll
            for (int i = 0; i < 8; i++)
#pragma unroll
                for (int j = 0; j < 8; j++) acc[i][j] += a[i] * b[j];
        }
        __syncthreads();
    }
#pragma unroll
    for (int i = 0; i < 8; i++) {
        int gi = i0 + r + i;
        if (gi < 289) {
#pragma unroll
            for (int j = 0; j < 8; j++) {
                float v = acc[i][j];
                if (gi == 288) v += b2[c + j];
                g_fold[gi * D + c + j] = v;
            }
        }
    }
}

// ---------------- K2: node pre-GEMM  A = x@fold[0:128], B = x@fold[128:256] -----
__global__ __launch_bounds__(256) void node_pre_kernel(const float* __restrict__ x, int N)
{
    __shared__ float aS[128 * ASTR];
    __shared__ float wS[32 * D];
    int tid = threadIdx.x;
    int tx = tid & 15, ty = tid >> 4;
    int r = ty * 8, c = tx * 8;
    int n0 = blockIdx.x * 128;
    int half = blockIdx.y;

    float acc[8][8];
#pragma unroll
    for (int i = 0; i < 8; i++)
#pragma unroll
        for (int j = 0; j < 8; j++) acc[i][j] = 0.f;

    for (int k0 = 0; k0 < 128; k0 += 32) {
#pragma unroll
        for (int l = 0; l < 4; l++) {
            int gid = tid + l * 256;
            int row = gid >> 3, c4 = (gid & 7) << 2;
            int gn = n0 + row;
            float4 v = make_float4(0.f, 0.f, 0.f, 0.f);
            if (gn < N) v = *(const float4*)&x[(size_t)gn * D + k0 + c4];
            *(float4*)&aS[row * ASTR + c4] = v;
        }
#pragma unroll
        for (int l = 0; l < 4; l++) {
            int gid = tid + l * 256;
            int kk = gid >> 5, j4 = (gid & 31) << 2;
            *(float4*)&wS[kk * D + j4] =
                *(const float4*)&g_fold[(half * 128 + k0 + kk) * D + j4];
        }
        __syncthreads();
#pragma unroll 4
        for (int kk = 0; kk < 32; kk++) {
            float a[8], b[8];
#pragma unroll
            for (int i = 0; i < 8; i++) a[i] = aS[(r + i) * ASTR + kk];
            *(float4*)&b[0] = *(float4*)&wS[kk * D + c];
            *(float4*)&b[4] = *(float4*)&wS[kk * D + c + 4];
#pragma unroll
            for (int i = 0; i < 8; i++)
#pragma unroll
                for (int j = 0; j < 8; j++) acc[i][j] += a[i] * b[j];
        }
        __syncthreads();
    }
    float* dst = half ? g_B : g_A;
#pragma unroll
    for (int i = 0; i < 8; i++) {
        int gn = n0 + r + i;
        if (gn < N) {
            *(float4*)&dst[(size_t)gn * D + c]     = make_float4(acc[i][0], acc[i][1], acc[i][2], acc[i][3]);
            *(float4*)&dst[(size_t)gn * D + c + 4] = make_float4(acc[i][4], acc[i][5], acc[i][6], acc[i][7]);
        }
    }
}

// ---------------- K3: edge kernel: z=A[src]+B[dst]+attr@U+c2; scatter sigmoid(z) -
__global__ __launch_bounds__(256) void edge_kernel(
    const float* __restrict__ attr, const void* __restrict__ eidx_raw,
    int Ecnt, int N)
{
    __shared__ float attrT[32][TSTR];
    __shared__ float U_s[32][128];
    __shared__ float c2_s[128];
    __shared__ int srcS[128], dstS[128];

    int tid = threadIdx.x;
    int tx = tid & 15, ty = tid >> 4;
    int r = ty * 8, c = tx * 8;
    int e0 = blockIdx.x * 128;
    int is64 = g_idx64;

    if (tid < 128) {
        int e = e0 + tid;
        int sv = 0, dv = 0;
        if (e < Ecnt) {
            if (is64) {
                sv = (int)((const long long*)eidx_raw)[e];
                dv = (int)((const long long*)eidx_raw)[(size_t)Ecnt + e];
            } else {
                sv = ((const int*)eidx_raw)[e];
                dv = ((const int*)eidx_raw)[(size_t)Ecnt + e];
            }
            // clamp: never crash on a bad index; wrong result is diagnosable
            sv = (sv < 0) ? 0 : (sv >= N ? N - 1 : sv);
            dv = (dv < 0) ? 0 : (dv >= N ? N - 1 : dv);
        }
        srcS[tid] = sv;
        dstS[tid] = dv;
    }
#pragma unroll
    for (int l = 0; l < 4; l++) {
        int gid = tid + l * 256;            // 128 edges x 8 float4
        int e = gid >> 3, k4 = (gid & 7) << 2;
        float4 v = make_float4(0.f, 0.f, 0.f, 0.f);
        if (e0 + e < Ecnt) v = *(const float4*)&attr[(size_t)(e0 + e) * DE + k4];
        attrT[k4 + 0][e] = v.x;
        attrT[k4 + 1][e] = v.y;
        attrT[k4 + 2][e] = v.z;
        attrT[k4 + 3][e] = v.w;
    }
#pragma unroll
    for (int l = 0; l < 4; l++) {
        int gid = tid + l * 256;            // 32 x 32 float4
        int kk = gid >> 5, j4 = (gid & 31) << 2;
        *(float4*)&U_s[kk][j4] = *(const float4*)&g_fold[(256 + kk) * D + j4];
    }
    if (tid < 32) *(float4*)&c2_s[tid * 4] = *(const float4*)&g_fold[288 * D + tid * 4];
    __syncthreads();

    float cv[8];
    *(float4*)&cv[0] = *(float4*)&c2_s[c];
    *(float4*)&cv[4] = *(float4*)&c2_s[c + 4];

    float acc[8][8];
#pragma unroll
    for (int i = 0; i < 8; i++) {
        int e = e0 + r + i;
        if (e < Ecnt) {
            int s = srcS[r + i], dd = dstS[r + i];
            float4 a0 = *(const float4*)&g_A[(size_t)s * D + c];
            float4 a1 = *(const float4*)&g_A[(size_t)s * D + c + 4];
            float4 b0 = *(const float4*)&g_B[(size_t)dd * D + c];
            float4 b1 = *(const float4*)&g_B[(size_t)dd * D + c + 4];
            acc[i][0] = a0.x + b0.x + cv[0]; acc[i][1] = a0.y + b0.y + cv[1];
            acc[i][2] = a0.z + b0.z + cv[2]; acc[i][3] = a0.w + b0.w + cv[3];
            acc[i][4] = a1.x + b1.x + cv[4]; acc[i][5] = a1.y + b1.y + cv[5];
            acc[i][6] = a1.z + b1.z + cv[6]; acc[i][7] = a1.w + b1.w + cv[7];
        } else {
#pragma unroll
            for (int j = 0; j < 8; j++) acc[i][j] = 0.f;
        }
    }
#pragma unroll 4
    for (int kk = 0; kk < 32; kk++) {
        float a[8], b[8];
        *(float4*)&a[0] = *(float4*)&attrT[kk][r];
        *(float4*)&a[4] = *(float4*)&attrT[kk][r + 4];
        *(float4*)&b[0] = *(float4*)&U_s[kk][c];
        *(float4*)&b[4] = *(float4*)&U_s[kk][c + 4];
#pragma unroll
        for (int i = 0; i < 8; i++)
#pragma unroll
            for (int j = 0; j < 8; j++) acc[i][j] += a[i] * b[j];
    }
#pragma unroll
    for (int i = 0; i < 8; i++) {
        int e = e0 + r + i;
        if (e < Ecnt) {
            int dd = dstS[r + i];
            float* p = &g_agg[(size_t)dd * D + c];
            red_add_v4(p,     sigm(acc[i][0]), sigm(acc[i][1]), sigm(acc[i][2]), sigm(acc[i][3]));
            red_add_v4(p + 4, sigm(acc[i][4]), sigm(acc[i][5]), sigm(acc[i][6]), sigm(acc[i][7]));
        }
    }
    if (tid < 128 && e0 + tid < Ecnt)
        atomicAdd(&g_cnt[dstS[tid]], 1.0f);
}

// ---------------- K4: node kernel: dh=(agg/cnt)@W3+b3; LN; FFN; LN ---------------
__global__ __launch_bounds__(256) void node_kernel(
    const float* __restrict__ x,
    const float* __restrict__ W3,  const float* __restrict__ b3,
    const float* __restrict__ Wf1, const float* __restrict__ bf1,
    const float* __restrict__ Wf2, const float* __restrict__ bf2,
    const float* __restrict__ g0,  const float* __restrict__ be0,
    const float* __restrict__ g1,  const float* __restrict__ be1,
    float* __restrict__ out, int N)
{
    extern __shared__ float sm[];
    float* hS    = sm;                     // 128*HSTR
    float* sS    = hS + 128 * HSTR;        // 128*HSTR
    float* aS    = sS + 128 * HSTR;        // 128*ASTR
    float* wS    = aS + 128 * ASTR;        // 32*D
    float* rinvS = wS + 32 * D;            // 128
    float* maskS = rinvS + 128;            // 128
    float* muS   = maskS + 128;            // 128
    float* rsS   = muS + 128;              // 128

    int tid = threadIdx.x;
    int tx = tid & 15, ty = tid >> 4;
    int r = ty * 8, c = tx * 8;
    int n0 = blockIdx.x * 128;

    if (tid < 128) {
        int gn = n0 + tid;
        float cf = (gn < N) ? g_cnt[gn] : 0.f;
        rinvS[tid] = __fdividef(1.0f, fmaxf(cf, 1.0f));
        maskS[tid] = (cf > 0.f) ? 1.f : 0.f;
    }
    __syncthreads();

    float acc[8][8];
#pragma unroll
    for (int i = 0; i < 8; i++)
#pragma unroll
        for (int j = 0; j < 8; j++) acc[i][j] = 0.f;

    // GEMM1: dh = (agg * rinv) @ W3
    for (int k0 = 0; k0 < 128; k0 += 32) {
#pragma unroll
        for (int l = 0; l < 4; l++) {
            int gid = tid + l * 256;
            int row = gid >> 3, c4 = (gid & 7) << 2;
            int gn = n0 + row;
            float4 v = make_float4(0.f, 0.f, 0.f, 0.f);
            if (gn < N) v = *(const float4*)&g_agg[(size_t)gn * D + k0 + c4];
            float ri = rinvS[row];
            v.x *= ri; v.y *= ri; v.z *= ri; v.w *= ri;
            *(float4*)&aS[row * ASTR + c4] = v;
        }
#pragma unroll
        for (int l = 0; l < 4; l++) {
            int gid = tid + l * 256;
            int kk = gid >> 5, j4 = (gid & 31) << 2;
            *(float4*)&wS[kk * D + j4] = *(const float4*)&W3[(k0 + kk) * D + j4];
        }
        __syncthreads();
#pragma unroll 4
        for (int kk = 0; kk < 32; kk++) {
            float a[8], b[8];
#pragma unroll
            for (int i = 0; i < 8; i++) a[i] = aS[(r + i) * ASTR + kk];
            *(float4*)&b[0] = *(float4*)&wS[kk * D + c];
            *(float4*)&b[4] = *(float4*)&wS[kk * D + c + 4];
#pragma unroll
            for (int i = 0; i < 8; i++)
#pragma unroll
                for (int j = 0; j < 8; j++) acc[i][j] += a[i] * b[j];
        }
        __syncthreads();
    }

    // h_pre = x + dh + b3*[cnt>0]  -> hS
    {
        float bl[8];
        *(float4*)&bl[0] = *(const float4*)&b3[c];
        *(float4*)&bl[4] = *(const float4*)&b3[c + 4];
#pragma unroll
        for (int i = 0; i < 8; i++) {
            int gn = n0 + r + i;
            float xv[8];
#pragma unroll
            for (int j = 0; j < 8; j++) xv[j] = 0.f;
            if (gn < N) {
                *(float4*)&xv[0] = *(const float4*)&x[(size_t)gn * D + c];
                *(float4*)&xv[4] = *(const float4*)&x[(size_t)gn * D + c + 4];
            }
            float mk = maskS[r + i];
#pragma unroll
            for (int j = 0; j < 8; j++)
                hS[(r + i) * HSTR + c + j] = xv[j] + acc[i][j] + bl[j] * mk;
        }
    }
    __syncthreads();

    // LN0 over hS rows, in place
    if (tid < 128) {
        const float* p = hS + tid * HSTR;
        float s = 0.f, q = 0.f;
#pragma unroll 8
        for (int k = 0; k < 128; k++) { float v = p[k]; s += v; q += v * v; }
        float mu = s * (1.f / 128.f);
        float var = fmaxf(q * (1.f / 128.f) - mu * mu, 0.f);
        muS[tid] = mu;
        rsS[tid] = rsqrtf(var + EPSF);
    }
    __syncthreads();
    {
        int col = tid & 127;
        float gg = g0[col], bb = be0[col];
        int rbase = tid >> 7;
#pragma unroll 8
        for (int l = 0; l < 64; l++) {
            int row = rbase + l * 2;
            float v = hS[row * HSTR + col];
            hS[row * HSTR + col] = (v - muS[row]) * rsS[row] * gg + bb;
        }
    }
    __syncthreads();

    // FFN: ff = sigmoid(h@Wf1+bf1)@Wf2  (4 chunks of 128 hidden cols)
    float ffacc[8][8];
#pragma unroll
    for (int i = 0; i < 8; i++)
#pragma unroll
        for (int j = 0; j < 8; j++) ffacc[i][j] = 0.f;

    for (int cc = 0; cc < 4; cc++) {
#pragma unroll
        for (int i = 0; i < 8; i++)
#pragma unroll
            for (int j = 0; j < 8; j++) acc[i][j] = 0.f;

        for (int k0 = 0; k0 < 128; k0 += 32) {
#pragma unroll
            for (int l = 0; l < 4; l++) {
                int gid = tid + l * 256;
                int kk = gid >> 5, j4 = (gid & 31) << 2;
                *(float4*)&wS[kk * D + j4] =
                    *(const float4*)&Wf1[(size_t)(k0 + kk) * HIDN + cc * 128 + j4];
            }
            __syncthreads();
#pragma unroll 4
            for (int kk = 0; kk < 32; kk++) {
                float a[8], b[8];
#pragma unroll
                for (int i = 0; i < 8; i++) a[i] = hS[(r + i) * HSTR + k0 + kk];
                *(float4*)&b[0] = *(float4*)&wS[kk * D + c];
                *(float4*)&b[4] = *(float4*)&wS[kk * D + c + 4];
#pragma unroll
                for (int i = 0; i < 8; i++)
#pragma unroll
                    for (int j = 0; j < 8; j++) acc[i][j] += a[i] * b[j];
            }
            __syncthreads();
        }
        {
            float bfl[8];
            *(float4*)&bfl[0] = *(const float4*)&bf1[cc * 128 + c];
            *(float4*)&bfl[4] = *(const float4*)&bf1[cc * 128 + c + 4];
#pragma unroll
            for (int i = 0; i < 8; i++)
#pragma unroll
                for (int j = 0; j < 8; j++)
                    sS[(r + i) * HSTR + c + j] = sigm(acc[i][j] + bfl[j]);
        }
        __syncthreads();

        for (int k0 = 0; k0 < 128; k0 += 32) {
#pragma unroll
            for (int l = 0; l < 4; l++) {
                int gid = tid + l * 256;
                int kk = gid >> 5, j4 = (gid & 31) << 2;
                *(float4*)&wS[kk * D + j4] =
                    *(const float4*)&Wf2[(size_t)(cc * 128 + k0 + kk) * D + j4];
            }
            __syncthreads();
#pragma unroll 4
            for (int kk = 0; kk < 32; kk++) {
                float a[8], b[8];
#pragma unroll
                for (int i = 0; i < 8; i++) a[i] = sS[(r + i) * HSTR + k0 + kk];
                *(float4*)&b[0] = *(float4*)&wS[kk * D + c];
                *(float4*)&b[4] = *(float4*)&wS[kk * D + c + 4];
#pragma unroll
                for (int i = 0; i < 8; i++)
#pragma unroll
                    for (int j = 0; j < 8; j++) ffacc[i][j] += a[i] * b[j];
            }
            __syncthreads();
        }
    }

    // pre-LN2 = h + ff + bf2 -> sS
    {
        float bfl[8];
        *(float4*)&bfl[0] = *(const float4*)&bf2[c];
        *(float4*)&bfl[4] = *(const float4*)&bf2[c + 4];
#pragma unroll
        for (int i = 0; i < 8; i++)
#pragma unroll
            for (int j = 0; j < 8; j++)
                sS[(r + i) * HSTR + c + j] =
                    hS[(r + i) * HSTR + c + j] + ffacc[i][j] + bfl[j];
    }
    __syncthreads();

    if (tid < 128) {
        const float* p = sS + tid * HSTR;
        float s = 0.f, q = 0.f;
#pragma unroll 8
        for (int k = 0; k < 128; k++) { float v = p[k]; s += v; q += v * v; }
        float mu = s * (1.f / 128.f);
        float var = fmaxf(q * (1.f / 128.f) - mu * mu, 0.f);
        muS[tid] = mu;
        rsS[tid] = rsqrtf(var + EPSF);
    }
    __syncthreads();
    {
        int col = tid & 127;
        float gg = g1[col], bb = be1[col];
        int rbase = tid >> 7;
#pragma unroll 8
        for (int l = 0; l < 64; l++) {
            int row = rbase + l * 2;
            int gn = n0 + row;
            if (gn < N) {
                float v = sS[row * HSTR + col];
                out[(size_t)gn * D + col] = (v - muS[row]) * rsS[row] * gg + bb;
            }
        }
    }
}

// ---------------- launch ---------------------------------------------------------
extern "C" void kernel_launch(void* const* d_in, const int* in_sizes, int n_in,
                              void* d_out, int out_size)
{
    const float* x    = (const float*)d_in[0];
    const float* attr = (const float*)d_in[1];
    const void*  eidx = d_in[2];
    const float* W1  = (const float*)d_in[3];
    const float* b1  = (const float*)d_in[4];
    const float* W2  = (const float*)d_in[5];
    const float* b2  = (const float*)d_in[6];
    const float* W3  = (const float*)d_in[7];
    const float* b3  = (const float*)d_in[8];
    const float* Wf1 = (const float*)d_in[9];
    const float* bf1 = (const float*)d_in[10];
    const float* Wf2 = (const float*)d_in[11];
    const float* bf2 = (const float*)d_in[12];
    const float* g0  = (const float*)d_in[13];
    const float* be0 = (const float*)d_in[14];
    const float* g1  = (const float*)d_in[15];
    const float* be1 = (const float*)d_in[16];
    float* out = (float*)d_out;

    int N = in_sizes[0] / D;
    int E = in_sizes[1] / DE;

    const int node_smem = (2 * 128 * HSTR + 128 * ASTR + 32 * D + 4 * 128) * (int)sizeof(float);
    cudaFuncSetAttribute(node_kernel, cudaFuncAttributeMaxDynamicSharedMemorySize, node_smem);

    void* aggp = nullptr; cudaGetSymbolAddress(&aggp, g_agg);
    void* cntp = nullptr; cudaGetSymbolAddress(&cntp, g_cnt);
    cudaMemsetAsync(aggp, 0, (size_t)N * D * sizeof(float), 0);
    cudaMemsetAsync(cntp, 0, (size_t)N * sizeof(float), 0);

    int ntiles = (N + 127) / 128;
    int etiles = (E + 127) / 128;

    detect_idx_kernel<<<1, 32>>>((const int*)eidx, E);
    fold_kernel<<<3, 256>>>(W1, b1, W2, b2);
    node_pre_kernel<<<dim3(ntiles, 2), 256>>>(x, N);
    edge_kernel<<<etiles, 256>>>(attr, eidx, E, N);
    node_kernel<<<ntiles, 256, node_smem>>>(x, W3, b3, Wf1, bf1, Wf2, bf2,
                                            g0, be0, g1, be1, out, N);
}

// round 5
// speedup vs baseline: 1.0002x; 1.0002x over previous
#include <cuda_runtime.h>
#include <cstdint>
#include <cstddef>

#define D    128
#define DE   32
#define HIDN 512
#define MAXN 100000
#define MAXE 1000000
#define EPSF 1e-5f

#define HSTR 133   // padded row stride for LN buffers (conflict-free column reads)
#define ASTR 36    // padded row stride for A-staging tiles (float4-aligned)
#define EB   64    // edges per block in edge_kernel
#define TSTR (EB + 4)  // attr transpose tile stride (68: 16B-aligned rows)

// ---------------- scratch (static device allocations; no cudaMalloc) ------------
__device__ float g_fold[289 * D];         // [W1;b1] @ W2  (+b2 on row 288)
__device__ float g_A[(size_t)MAXN * D];   // x @ (W1a@W2)  gathered by src
__device__ float g_B[(size_t)MAXN * D];   // x @ (W1b@W2)  gathered by dst
__device__ float g_agg[(size_t)MAXN * D]; // segment_sum(sigmoid(z))
__device__ float g_cnt[MAXN];
__device__ int   g_idx64;                 // 1 if edge_index buffer is int64

__device__ __forceinline__ float sigm(float z) {
    return __fdividef(1.0f, 1.0f + __expf(-z));
}

__device__ __forceinline__ void red_add_v4(float* p, float a, float b, float c, float d) {
    asm volatile("red.global.add.v4.f32 [%0], {%1, %2, %3, %4};"
                 :: "l"(p), "f"(a), "f"(b), "f"(c), "f"(d) : "memory");
}

// ---------------- K1: fold kernel  C[289x128] = [W1;b1] @ W2 (+b2 on bias row) ---
// Also performs edge_index dtype detection (block 0, thread 0):
// int64 little-endian values < 2^31 have every odd 32-bit word == 0;
// for int32 data those words are independent indices (P(all 0) ~ 0).
__global__ __launch_bounds__(256) void fold_kernel(
    const float* __restrict__ W1, const float* __restrict__ b1,
    const float* __restrict__ W2, const float* __restrict__ b2,
    const int* __restrict__ eidx_w32, int Ecnt)
{
    if (blockIdx.x == 0 && threadIdx.x == 0) {
        int is64 = 1;
        int lim = (Ecnt < 64) ? Ecnt : 64;
        for (int i = 0; i < lim; i++)
            if (eidx_w32[2 * i + 1] != 0) { is64 = 0; break; }
        g_idx64 = is64;
    }

    __shared__ float aS[128 * ASTR];
    __shared__ float wS[32 * D];
    int tid = threadIdx.x;
    int tx = tid & 15, ty = tid >> 4;
    int r = ty * 8, c = tx * 8;
    int i0 = blockIdx.x * 128;

    float acc[8][8];
#pragma unroll
    for (int i = 0; i < 8; i++)
#pragma unroll
        for (int j = 0; j < 8; j++) acc[i][j] = 0.f;

    for (int k0 = 0; k0 < 128; k0 += 32) {
#pragma unroll
        for (int l = 0; l < 4; l++) {
            int gid = tid + l * 256;
            int row = gid >> 3, c4 = (gid & 7) << 2;
            int gi = i0 + row;
            float4 v = make_float4(0.f, 0.f, 0.f, 0.f);
            if (gi < 288)       v = *(const float4*)&W1[gi * D + k0 + c4];
            else if (gi == 288) v = *(const float4*)&b1[k0 + c4];
            *(float4*)&aS[row * ASTR + c4] = v;
        }
#pragma unroll
        for (int l = 0; l < 4; l++) {
            int gid = tid + l * 256;
            int kk = gid >> 5, j4 = (gid & 31) << 2;
            *(float4*)&wS[kk * D + j4] = *(const float4*)&W2[(k0 + kk) * D + j4];
        }
        __syncthreads();
#pragma unroll 4
        for (int kk = 0; kk < 32; kk++) {
            float a[8], b[8];
#pragma unroll
            for (int i = 0; i < 8; i++) a[i] = aS[(r + i) * ASTR + kk];
            *(float4*)&b[0] = *(float4*)&wS[kk * D + c];
            *(float4*)&b[4] = *(float4*)&wS[kk * D + c + 4];
#pragma unroll
            for (int i = 0; i < 8; i++)
#pragma unroll
                for (int j = 0; j < 8; j++) acc[i][j] += a[i] * b[j];
        }
        __syncthreads();
    }
#pragma unroll
    for (int i = 0; i < 8; i++) {
        int gi = i0 + r + i;
        if (gi < 289) {
#pragma unroll
            for (int j = 0; j < 8; j++) {
                float v = acc[i][j];
                if (gi == 288) v += b2[c + j];
                g_fold[gi * D + c + j] = v;
            }
        }
    }
}

// ---------------- K2: node pre-GEMM  A = x@fold[0:128], B = x@fold[128:256] -----
__global__ __launch_bounds__(256) void node_pre_kernel(const float* __restrict__ x, int N)
{
    __shared__ float aS[128 * ASTR];
    __shared__ float wS[32 * D];
    int tid = threadIdx.x;
    int tx = tid & 15, ty = tid >> 4;
    int r = ty * 8, c = tx * 8;
    int n0 = blockIdx.x * 128;
    int half = blockIdx.y;

    float acc[8][8];
#pragma unroll
    for (int i = 0; i < 8; i++)
#pragma unroll
        for (int j = 0; j < 8; j++) acc[i][j] = 0.f;

    for (int k0 = 0; k0 < 128; k0 += 32) {
#pragma unroll
        for (int l = 0; l < 4; l++) {
            int gid = tid + l * 256;
            int row = gid >> 3, c4 = (gid & 7) << 2;
            int gn = n0 + row;
            float4 v = make_float4(0.f, 0.f, 0.f, 0.f);
            if (gn < N) v = *(const float4*)&x[(size_t)gn * D + k0 + c4];
            *(float4*)&aS[row * ASTR + c4] = v;
        }
#pragma unroll
        for (int l = 0; l < 4; l++) {
            int gid = tid + l * 256;
            int kk = gid >> 5, j4 = (gid & 31) << 2;
            *(float4*)&wS[kk * D + j4] =
                *(const float4*)&g_fold[(half * 128 + k0 + kk) * D + j4];
        }
        __syncthreads();
#pragma unroll 4
        for (int kk = 0; kk < 32; kk++) {
            float a[8], b[8];
#pragma unroll
            for (int i = 0; i < 8; i++) a[i] = aS[(r + i) * ASTR + kk];
            *(float4*)&b[0] = *(float4*)&wS[kk * D + c];
            *(float4*)&b[4] = *(float4*)&wS[kk * D + c + 4];
#pragma unroll
            for (int i = 0; i < 8; i++)
#pragma unroll
                for (int j = 0; j < 8; j++) acc[i][j] += a[i] * b[j];
        }
        __syncthreads();
    }
    float* dst = half ? g_B : g_A;
#pragma unroll
    for (int i = 0; i < 8; i++) {
        int gn = n0 + r + i;
        if (gn < N) {
            *(float4*)&dst[(size_t)gn * D + c]     = make_float4(acc[i][0], acc[i][1], acc[i][2], acc[i][3]);
            *(float4*)&dst[(size_t)gn * D + c + 4] = make_float4(acc[i][4], acc[i][5], acc[i][6], acc[i][7]);
        }
    }
}

// ---------------- K3: edge kernel: z=A[src]+B[dst]+attr@U+c2; scatter sigmoid(z) -
// 64 edges per block, 4 edges x 8 cols per thread (occupancy-optimized).
__global__ __launch_bounds__(256, 3) void edge_kernel(
    const float* __restrict__ attr, const void* __restrict__ eidx_raw,
    int Ecnt, int N)
{
    __shared__ float attrT[32][TSTR];
    __shared__ float U_s[32][128];
    __shared__ float c2_s[128];
    __shared__ int srcS[EB], dstS[EB];

    int tid = threadIdx.x;
    int tx = tid & 15, ty = tid >> 4;
    int r = ty * 4, c = tx * 8;
    int e0 = blockIdx.x * EB;
    int is64 = g_idx64;

    if (tid < EB) {
        int e = e0 + tid;
        int sv = 0, dv = 0;
        if (e < Ecnt) {
            if (is64) {
                sv = (int)((const long long*)eidx_raw)[e];
                dv = (int)((const long long*)eidx_raw)[(size_t)Ecnt + e];
            } else {
                sv = ((const int*)eidx_raw)[e];
                dv = ((const int*)eidx_raw)[(size_t)Ecnt + e];
            }
            // clamp: never crash on a bad index; wrong result is diagnosable
            sv = (sv < 0) ? 0 : (sv >= N ? N - 1 : sv);
            dv = (dv < 0) ? 0 : (dv >= N ? N - 1 : dv);
        }
        srcS[tid] = sv;
        dstS[tid] = dv;
    }
#pragma unroll
    for (int l = 0; l < 2; l++) {
        int gid = tid + l * 256;            // 64 edges x 8 float4
        int e = gid >> 3, k4 = (gid & 7) << 2;
        float4 v = make_float4(0.f, 0.f, 0.f, 0.f);
        if (e0 + e < Ecnt) v = *(const float4*)&attr[(size_t)(e0 + e) * DE + k4];
        attrT[k4 + 0][e] = v.x;
        attrT[k4 + 1][e] = v.y;
        attrT[k4 + 2][e] = v.z;
        attrT[k4 + 3][e] = v.w;
    }
#pragma unroll
    for (int l = 0; l < 4; l++) {
        int gid = tid + l * 256;            // 32 x 32 float4
        int kk = gid >> 5, j4 = (gid & 31) << 2;
        *(float4*)&U_s[kk][j4] = *(const float4*)&g_fold[(256 + kk) * D + j4];
    }
    if (tid < 32) *(float4*)&c2_s[tid * 4] = *(const float4*)&g_fold[288 * D + tid * 4];
    __syncthreads();

    float cv[8];
    *(float4*)&cv[0] = *(float4*)&c2_s[c];
    *(float4*)&cv[4] = *(float4*)&c2_s[c + 4];

    float acc[4][8];
#pragma unroll
    for (int i = 0; i < 4; i++) {
        int e = e0 + r + i;
        if (e < Ecnt) {
            int s = srcS[r + i], dd = dstS[r + i];
            float4 a0 = *(const float4*)&g_A[(size_t)s * D + c];
            float4 a1 = *(const float4*)&g_A[(size_t)s * D + c + 4];
            float4 b0 = *(const float4*)&g_B[(size_t)dd * D + c];
            float4 b1 = *(const float4*)&g_B[(size_t)dd * D + c + 4];
            acc[i][0] = a0.x + b0.x + cv[0]; acc[i][1] = a0.y + b0.y + cv[1];
            acc[i][2] = a0.z + b0.z + cv[2]; acc[i][3] = a0.w + b0.w + cv[3];
            acc[i][4] = a1.x + b1.x + cv[4]; acc[i][5] = a1.y + b1.y + cv[5];
            acc[i][6] = a1.z + b1.z + cv[6]; acc[i][7] = a1.w + b1.w + cv[7];
        } else {
#pragma unroll
            for (int j = 0; j < 8; j++) acc[i][j] = 0.f;
        }
    }
#pragma unroll 4
    for (int kk = 0; kk < 32; kk++) {
        float a[4], b[8];
        *(float4*)&a[0] = *(float4*)&attrT[kk][r];
        *(float4*)&b[0] = *(float4*)&U_s[kk][c];
        *(float4*)&b[4] = *(float4*)&U_s[kk][c + 4];
#pragma unroll
        for (int i = 0; i < 4; i++)
#pragma unroll
            for (int j = 0; j < 8; j++) acc[i][j] += a[i] * b[j];
    }
#pragma unroll
    for (int i = 0; i < 4; i++) {
        int e = e0 + r + i;
        if (e < Ecnt) {
            int dd = dstS[r + i];
            float* p = &g_agg[(size_t)dd * D + c];
            red_add_v4(p,     sigm(acc[i][0]), sigm(acc[i][1]), sigm(acc[i][2]), sigm(acc[i][3]));
            red_add_v4(p + 4, sigm(acc[i][4]), sigm(acc[i][5]), sigm(acc[i][6]), sigm(acc[i][7]));
        }
    }
    if (tid < EB && e0 + tid < Ecnt)
        atomicAdd(&g_cnt[dstS[tid]], 1.0f);
}

// ---------------- K4: node kernel: dh=(agg/cnt)@W3+b3; LN; FFN; LN ---------------
__global__ __launch_bounds__(256) void node_kernel(
    const float* __restrict__ x,
    const float* __restrict__ W3,  const float* __restrict__ b3,
    const float* __restrict__ Wf1, const float* __restrict__ bf1,
    const float* __restrict__ Wf2, const float* __restrict__ bf2,
    const float* __restrict__ g0,  const float* __restrict__ be0,
    const float* __restrict__ g1,  const float* __restrict__ be1,
    float* __restrict__ out, int N)
{
    extern __shared__ float sm[];
    float* hS    = sm;                     // 128*HSTR
    float* sS    = hS + 128 * HSTR;        // 128*HSTR
    float* aS    = sS + 128 * HSTR;        // 128*ASTR
    float* wS    = aS + 128 * ASTR;        // 32*D
    float* rinvS = wS + 32 * D;            // 128
    float* maskS = rinvS + 128;            // 128
    float* muS   = maskS + 128;            // 128
    float* rsS   = muS + 128;              // 128

    int tid = threadIdx.x;
    int tx = tid & 15, ty = tid >> 4;
    int r = ty * 8, c = tx * 8;
    int n0 = blockIdx.x * 128;

    if (tid < 128) {
        int gn = n0 + tid;
        float cf = (gn < N) ? g_cnt[gn] : 0.f;
        rinvS[tid] = __fdividef(1.0f, fmaxf(cf, 1.0f));
        maskS[tid] = (cf > 0.f) ? 1.f : 0.f;
    }
    __syncthreads();

    float acc[8][8];
#pragma unroll
    for (int i = 0; i < 8; i++)
#pragma unroll
        for (int j = 0; j < 8; j++) acc[i][j] = 0.f;

    // GEMM1: dh = (agg * rinv) @ W3
    for (int k0 = 0; k0 < 128; k0 += 32) {
#pragma unroll
        for (int l = 0; l < 4; l++) {
            int gid = tid + l * 256;
            int row = gid >> 3, c4 = (gid & 7) << 2;
            int gn = n0 + row;
            float4 v = make_float4(0.f, 0.f, 0.f, 0.f);
            if (gn < N) v = *(const float4*)&g_agg[(size_t)gn * D + k0 + c4];
            float ri = rinvS[row];
            v.x *= ri; v.y *= ri; v.z *= ri; v.w *= ri;
            *(float4*)&aS[row * ASTR + c4] = v;
        }
#pragma unroll
        for (int l = 0; l < 4; l++) {
            int gid = tid + l * 256;
            int kk = gid >> 5, j4 = (gid & 31) << 2;
            *(float4*)&wS[kk * D + j4] = *(const float4*)&W3[(k0 + kk) * D + j4];
        }
        __syncthreads();
#pragma unroll 4
        for (int kk = 0; kk < 32; kk++) {
            float a[8], b[8];
#pragma unroll
            for (int i = 0; i < 8; i++) a[i] = aS[(r + i) * ASTR + kk];
            *(float4*)&b[0] = *(float4*)&wS[kk * D + c];
            *(float4*)&b[4] = *(float4*)&wS[kk * D + c + 4];
#pragma unroll
            for (int i = 0; i < 8; i++)
#pragma unroll
                for (int j = 0; j < 8; j++) acc[i][j] += a[i] * b[j];
        }
        __syncthreads();
    }

    // h_pre = x + dh + b3*[cnt>0]  -> hS
    {
        float bl[8];
        *(float4*)&bl[0] = *(const float4*)&b3[c];
        *(float4*)&bl[4] = *(const float4*)&b3[c + 4];
#pragma unroll
        for (int i = 0; i < 8; i++) {
            int gn = n0 + r + i;
            float xv[8];
#pragma unroll
            for (int j = 0; j < 8; j++) xv[j] = 0.f;
            if (gn < N) {
                *(float4*)&xv[0] = *(const float4*)&x[(size_t)gn * D + c];
                *(float4*)&xv[4] = *(const float4*)&x[(size_t)gn * D + c + 4];
            }
            float mk = maskS[r + i];
#pragma unroll
            for (int j = 0; j < 8; j++)
                hS[(r + i) * HSTR + c + j] = xv[j] + acc[i][j] + bl[j] * mk;
        }
    }
    __syncthreads();

    // LN0 over hS rows, in place
    if (tid < 128) {
        const float* p = hS + tid * HSTR;
        float s = 0.f, q = 0.f;
#pragma unroll 8
        for (int k = 0; k < 128; k++) { float v = p[k]; s += v; q += v * v; }
        float mu = s * (1.f / 128.f);
        float var = fmaxf(q * (1.f / 128.f) - mu * mu, 0.f);
        muS[tid] = mu;
        rsS[tid] = rsqrtf(var + EPSF);
    }
    __syncthreads();
    {
        int col = tid & 127;
        float gg = g0[col], bb = be0[col];
        int rbase = tid >> 7;
#pragma unroll 8
        for (int l = 0; l < 64; l++) {
            int row = rbase + l * 2;
            float v = hS[row * HSTR + col];
            hS[row * HSTR + col] = (v - muS[row]) * rsS[row] * gg + bb;
        }
    }
    __syncthreads();

    // FFN: ff = sigmoid(h@Wf1+bf1)@Wf2  (4 chunks of 128 hidden cols)
    float ffacc[8][8];
#pragma unroll
    for (int i = 0; i < 8; i++)
#pragma unroll
        for (int j = 0; j < 8; j++) ffacc[i][j] = 0.f;

    for (int cc = 0; cc < 4; cc++) {
#pragma unroll
        for (int i = 0; i < 8; i++)
#pragma unroll
            for (int j = 0; j < 8; j++) acc[i][j] = 0.f;

        for (int k0 = 0; k0 < 128; k0 += 32) {
#pragma unroll
            for (int l = 0; l < 4; l++) {
                int gid = tid + l * 256;
                int kk = gid >> 5, j4 = (gid & 31) << 2;
                *(float4*)&wS[kk * D + j4] =
                    *(const float4*)&Wf1[(size_t)(k0 + kk) * HIDN + cc * 128 + j4];
            }
            __syncthreads();
#pragma unroll 4
            for (int kk = 0; kk < 32; kk++) {
                float a[8], b[8];
#pragma unroll
                for (int i = 0; i < 8; i++) a[i] = hS[(r + i) * HSTR + k0 + kk];
                *(float4*)&b[0] = *(float4*)&wS[kk * D + c];
                *(float4*)&b[4] = *(float4*)&wS[kk * D + c + 4];
#pragma unroll
                for (int i = 0; i < 8; i++)
#pragma unroll
                    for (int j = 0; j < 8; j++) acc[i][j] += a[i] * b[j];
            }
            __syncthreads();
        }
        {
            float bfl[8];
            *(float4*)&bfl[0] = *(const float4*)&bf1[cc * 128 + c];
            *(float4*)&bfl[4] = *(const float4*)&bf1[cc * 128 + c + 4];
#pragma unroll
            for (int i = 0; i < 8; i++)
#pragma unroll
                for (int j = 0; j < 8; j++)
                    sS[(r + i) * HSTR + c + j] = sigm(acc[i][j] + bfl[j]);
        }
        __syncthreads();

        for (int k0 = 0; k0 < 128; k0 += 32) {
#pragma unroll
            for (int l = 0; l < 4; l++) {
                int gid = tid + l * 256;
                int kk = gid >> 5, j4 = (gid & 31) << 2;
                *(float4*)&wS[kk * D + j4] =
                    *(const float4*)&Wf2[(size_t)(cc * 128 + k0 + kk) * D + j4];
            }
            __syncthreads();
#pragma unroll 4
            for (int kk = 0; kk < 32; kk++) {
                float a[8], b[8];
#pragma unroll
                for (int i = 0; i < 8; i++) a[i] = sS[(r + i) * HSTR + k0 + kk];
                *(float4*)&b[0] = *(float4*)&wS[kk * D + c];
                *(float4*)&b[4] = *(float4*)&wS[kk * D + c + 4];
#pragma unroll
                for (int i = 0; i < 8; i++)
#pragma unroll
                    for (int j = 0; j < 8; j++) ffacc[i][j] += a[i] * b[j];
            }
            __syncthreads();
        }
    }

    // pre-LN2 = h + ff + bf2 -> sS
    {
        float bfl[8];
        *(float4*)&bfl[0] = *(const float4*)&bf2[c];
        *(float4*)&bfl[4] = *(const float4*)&bf2[c + 4];
#pragma unroll
        for (int i = 0; i < 8; i++)
#pragma unroll
            for (int j = 0; j < 8; j++)
                sS[(r + i) * HSTR + c + j] =
                    hS[(r + i) * HSTR + c + j] + ffacc[i][j] + bfl[j];
    }
    __syncthreads();

    if (tid < 128) {
        const float* p = sS + tid * HSTR;
        float s = 0.f, q = 0.f;
#pragma unroll 8
        for (int k = 0; k < 128; k++) { float v = p[k]; s += v; q += v * v; }
        float mu = s * (1.f / 128.f);
        float var = fmaxf(q * (1.f / 128.f) - mu * mu, 0.f);
        muS[tid] = mu;
        rsS[tid] = rsqrtf(var + EPSF);
    }
    __syncthreads();
    {
        int col = tid & 127;
        float gg = g1[col], bb = be1[col];
        int rbase = tid >> 7;
#pragma unroll 8
        for (int l = 0; l < 64; l++) {
            int row = rbase + l * 2;
            int gn = n0 + row;
            if (gn < N) {
                float v = sS[row * HSTR + col];
                out[(size_t)gn * D + col] = (v - muS[row]) * rsS[row] * gg + bb;
            }
        }
    }
}

// ---------------- launch ---------------------------------------------------------
extern "C" void kernel_launch(void* const* d_in, const int* in_sizes, int n_in,
                              void* d_out, int out_size)
{
    const float* x    = (const float*)d_in[0];
    const float* attr = (const float*)d_in[1];
    const void*  eidx = d_in[2];
    const float* W1  = (const float*)d_in[3];
    const float* b1  = (const float*)d_in[4];
    const float* W2  = (const float*)d_in[5];
    const float* b2  = (const float*)d_in[6];
    const float* W3  = (const float*)d_in[7];
    const float* b3  = (const float*)d_in[8];
    const float* Wf1 = (const float*)d_in[9];
    const float* bf1 = (const float*)d_in[10];
    const float* Wf2 = (const float*)d_in[11];
    const float* bf2 = (const float*)d_in[12];
    const float* g0  = (const float*)d_in[13];
    const float* be0 = (const float*)d_in[14];
    const float* g1  = (const float*)d_in[15];
    const float* be1 = (const float*)d_in[16];
    float* out = (float*)d_out;

    int N = in_sizes[0] / D;
    int E = in_sizes[1] / DE;

    const int node_smem = (2 * 128 * HSTR + 128 * ASTR + 32 * D + 4 * 128) * (int)sizeof(float);
    cudaFuncSetAttribute(node_kernel, cudaFuncAttributeMaxDynamicSharedMemorySize, node_smem);

    void* aggp = nullptr; cudaGetSymbolAddress(&aggp, g_agg);
    void* cntp = nullptr; cudaGetSymbolAddress(&cntp, g_cnt);
    cudaMemsetAsync(aggp, 0, (size_t)N * D * sizeof(float), 0);
    cudaMemsetAsync(cntp, 0, (size_t)N * sizeof(float), 0);

    int ntiles = (N + 127) / 128;
    int etiles = (E + EB - 1) / EB;

    fold_kernel<<<3, 256>>>(W1, b1, W2, b2, (const int*)eidx, E);
    node_pre_kernel<<<dim3(ntiles, 2), 256>>>(x, N);
    edge_kernel<<<etiles, 256>>>(attr, eidx, E, N);
    node_kernel<<<ntiles, 256, node_smem>>>(x, W3, b3, Wf1, bf1, Wf2, bf2,
                                            g0, be0, g1, be1, out, N);
}